// round 11
// baseline (speedup 1.0000x reference)
#include <cuda_runtime.h>
#include <cuda_bf16.h>
#include <math.h>

// SimDiff: right[f,i] = cos(x[f,i], x[f+iv, i+1])      (i < tpf-1)
//          down [f,i] = cos(x[f,i], x[f+iv, i+width])  (i < tpf-width)
// else -1. Output: [right | down], each frames*tpf f32.
//
// R10 (warp co-scheduling on the diagonal lattice) won at 37.4us but merged
// only ~12% of L2 traffic (warps de-phase over the chunk loop). This round:
//  - CW=1 x CL=8 tile: a CTA's 8 warps are 8 CONSECUTIVE steps of one chain.
//    Distinct streams/CTA = 9 anchors + 8 downs = 17 for 24 uses (2.125x).
//  - PHASE LOCK: __syncthreads() at chunk k=3 and k=6 keeps warps inside the
//    L1 reuse window. Tile body is non-divergent (invalid steps clamp token,
//    writes predicated) so every warp reaches every barrier.
//  - Uniform chain decode per CTA (one div/mod per tile, not per warp).

#define EPSN 1e-8f
#define CL 8   // chain steps (= warps) per CTA

template <int NPL>  // D = NPL * 128 floats
__global__ void __launch_bounds__(256, 6) simdiff_chainlock_kernel(
    const float* __restrict__ x,
    const int* __restrict__ p_frames,
    const int* __restrict__ p_height,
    const int* __restrict__ p_width,
    const int* __restrict__ p_interval,
    float* __restrict__ out,
    int total)
{
    const int width  = *p_width;
    const int height = *p_height;
    const int frames = *p_frames;
    const int iv     = *p_interval;
    const int tpf    = width * height;
    const int D      = NPL * 128;

    // Diagonal chains: step (f += iv, i += 1). Starts: f0 < iv (any i0),
    // or i0 == 0 (f0 in [iv, frames)). Every token lies on exactly one chain.
    const int nch_a = iv * tpf;
    const int nch_b = frames > iv ? frames - iv : 0;
    const int nch   = nch_a + nch_b;
    const int maxL  = min((frames + iv - 1) / iv, tpf);
    const int nsb   = (maxL + CL - 1) / CL;
    const long ntile = (long)nch * nsb;

    const int wib  = threadIdx.x >> 5;      // 0..7 = step offset in tile
    const int lane = threadIdx.x & 31;

    float* __restrict__ outR = out;
    float* __restrict__ outD = out + total;
    const int dtok = iv * tpf + 1;          // right-target token offset
    const int ctok = iv * tpf + width;      // down-target token offset

    for (long p = blockIdx.x; p < ntile; p += gridDim.x) {
        const int cb = (int)(p % nch);      // chain id (uniform in CTA)
        const int sb = (int)(p / nch);      // step block

        int f0, i0;
        if (cb < nch_a) { f0 = cb % iv; i0 = cb / iv; }
        else            { f0 = iv + (cb - nch_a); i0 = 0; }
        const bool chok = (f0 < frames) && (i0 < tpf);
        if (!chok) { f0 = 0; i0 = 0; }
        const int Lc = chok ? min((frames - f0 + iv - 1) / iv, tpf - i0) : 0;

        const int s   = sb * CL + wib;
        const bool sok = chok && (s < Lc);
        const int sc  = sok ? s : 0;        // clamp to a safe step

        const int fA = f0 + sc * iv;
        const int iA = i0 + sc;
        const int t  = fA * tpf + iA;

        const bool vf = sok && ((fA + iv) < frames);
        const bool vr = vf && (iA + 1 < tpf);
        const bool vd = vf && (iA < tpf - width);

        // Clamp invalid targets to the anchor; outputs fixed below.
        const int tb = vr ? t + dtok : t;
        const int tc = vd ? t + ctok : t;

        const float4* __restrict__ a4 =
            reinterpret_cast<const float4*>(x + (size_t)t * D) + lane;
        const float4* __restrict__ b4 =
            reinterpret_cast<const float4*>(x + (size_t)tb * D) + lane;
        const float4* __restrict__ c4 =
            reinterpret_cast<const float4*>(x + (size_t)tc * D) + lane;

        float na = 0.0f, d1 = 0.0f, n1 = 0.0f, d2 = 0.0f, n2 = 0.0f;

        // R2 body: depth-1 software pipeline, 3 loads always in flight.
        // Phase-lock barriers at k=3 and k=6 (all warps always reach them).
        float4 a = a4[0];
        float4 b = b4[0];
        float4 c = c4[0];
#pragma unroll
        for (int k = 0; k < NPL; k++) {
            if (k == 3 || k == 6) __syncthreads();
            float4 ac = a, bc = b, cc = c;
            if (k + 1 < NPL) {
                a = a4[32 * (k + 1)];
                b = b4[32 * (k + 1)];
                c = c4[32 * (k + 1)];
            }
            na = fmaf(ac.x, ac.x, na); na = fmaf(ac.y, ac.y, na);
            na = fmaf(ac.z, ac.z, na); na = fmaf(ac.w, ac.w, na);
            d1 = fmaf(ac.x, bc.x, d1); d1 = fmaf(ac.y, bc.y, d1);
            d1 = fmaf(ac.z, bc.z, d1); d1 = fmaf(ac.w, bc.w, d1);
            n1 = fmaf(bc.x, bc.x, n1); n1 = fmaf(bc.y, bc.y, n1);
            n1 = fmaf(bc.z, bc.z, n1); n1 = fmaf(bc.w, bc.w, n1);
            d2 = fmaf(ac.x, cc.x, d2); d2 = fmaf(ac.y, cc.y, d2);
            d2 = fmaf(ac.z, cc.z, d2); d2 = fmaf(ac.w, cc.w, d2);
            n2 = fmaf(cc.x, cc.x, n2); n2 = fmaf(cc.y, cc.y, n2);
            n2 = fmaf(cc.z, cc.z, n2); n2 = fmaf(cc.w, cc.w, n2);
        }

#pragma unroll
        for (int off = 16; off > 0; off >>= 1) {
            na += __shfl_xor_sync(0xFFFFFFFFu, na, off);
            d1 += __shfl_xor_sync(0xFFFFFFFFu, d1, off);
            n1 += __shfl_xor_sync(0xFFFFFFFFu, n1, off);
            d2 += __shfl_xor_sync(0xFFFFFFFFu, d2, off);
            n2 += __shfl_xor_sync(0xFFFFFFFFu, n2, off);
        }

        if (lane == 0 && sok) {
            const float nA = fmaxf(sqrtf(na), EPSN);
            outR[t] = vr ? d1 / (nA * fmaxf(sqrtf(n1), EPSN)) : -1.0f;
            outD[t] = vd ? d2 / (nA * fmaxf(sqrtf(n2), EPSN)) : -1.0f;
        }
    }
}

// Generic fallback for arbitrary D (scalar loads, one warp per token).
__global__ void __launch_bounds__(256) simdiff_generic_kernel(
    const float* __restrict__ x,
    const int* __restrict__ p_frames,
    const int* __restrict__ p_height,
    const int* __restrict__ p_width,
    const int* __restrict__ p_interval,
    float* __restrict__ out,
    int total, int D)
{
    const int gwarp = (blockIdx.x * blockDim.x + threadIdx.x) >> 5;
    const int lane  = threadIdx.x & 31;
    if (gwarp >= total) return;

    const int width    = *p_width;
    const int height   = *p_height;
    const int frames   = *p_frames;
    const int interval = *p_interval;
    const int tpf      = width * height;

    const int f = gwarp / tpf;
    const int i = gwarp - f * tpf;

    float* __restrict__ outR = out;
    float* __restrict__ outD = out + total;

    const bool vf = (f + interval) < frames;
    if (!vf) {
        if (lane == 0) { outR[gwarp] = -1.0f; outD[gwarp] = -1.0f; }
        return;
    }
    const bool vr = (i < tpf - 1);
    const bool vd = (i < tpf - width);

    const size_t bframe = (size_t)(f + interval) * tpf + i;
    const size_t i1 = vr ? (bframe + 1)     : bframe;
    const size_t i2 = vd ? (bframe + width) : bframe;

    const float* a = x + (size_t)gwarp * D;
    const float* b = x + i1 * D;
    const float* c = x + i2 * D;

    float na = 0.0f, d1 = 0.0f, n1 = 0.0f, d2 = 0.0f, n2 = 0.0f;
    for (int k = lane; k < D; k += 32) {
        float av = a[k], bv = b[k], cv = c[k];
        na = fmaf(av, av, na);
        d1 = fmaf(av, bv, d1); n1 = fmaf(bv, bv, n1);
        d2 = fmaf(av, cv, d2); n2 = fmaf(cv, cv, n2);
    }

#pragma unroll
    for (int off = 16; off > 0; off >>= 1) {
        na += __shfl_xor_sync(0xFFFFFFFFu, na, off);
        d1 += __shfl_xor_sync(0xFFFFFFFFu, d1, off);
        n1 += __shfl_xor_sync(0xFFFFFFFFu, n1, off);
        d2 += __shfl_xor_sync(0xFFFFFFFFu, d2, off);
        n2 += __shfl_xor_sync(0xFFFFFFFFu, n2, off);
    }

    if (lane == 0) {
        const float nA = fmaxf(sqrtf(na), EPSN);
        outR[gwarp] = vr ? d1 / (nA * fmaxf(sqrtf(n1), EPSN)) : -1.0f;
        outD[gwarp] = vd ? d2 / (nA * fmaxf(sqrtf(n2), EPSN)) : -1.0f;
    }
}

extern "C" void kernel_launch(void* const* d_in, const int* in_sizes, int n_in,
                              void* d_out, int out_size) {
    const float* x        = (const float*)d_in[0];
    const int* p_frames   = (const int*)d_in[1];
    const int* p_height   = (const int*)d_in[2];
    const int* p_width    = (const int*)d_in[3];
    const int* p_interval = (const int*)d_in[4];
    float* out = (float*)d_out;

    const int total = out_size / 2;            // frames * tpf
    const int D     = in_sizes[0] / total;     // hidden dim

    if (D == 1152 || D == 1024 || D == 1280) {
        // ntile ~ total/8 + chain-edge padding; grid-stride covers any
        // shape, surplus tiles exit at the loop bound immediately.
        const int blocks = total / 8 + 1280;
        if (D == 1152) {
            simdiff_chainlock_kernel<9><<<blocks, 256>>>(
                x, p_frames, p_height, p_width, p_interval, out, total);
        } else if (D == 1024) {
            simdiff_chainlock_kernel<8><<<blocks, 256>>>(
                x, p_frames, p_height, p_width, p_interval, out, total);
        } else {
            simdiff_chainlock_kernel<10><<<blocks, 256>>>(
                x, p_frames, p_height, p_width, p_interval, out, total);
        }
    } else {
        const int blocks = (total + 7) / 8;
        simdiff_generic_kernel<<<blocks, 256>>>(
            x, p_frames, p_height, p_width, p_interval, out, total, D);
    }
}